// round 11
// baseline (speedup 1.0000x reference)
#include <cuda_runtime.h>

#define NTOK   2048   // P*B
#define DMODEL 512
#define DHID   2048
#define NEXP   16

// ------------------------- device scratch (no allocs allowed) -------------
__device__ float g_He[NTOK * 2 * DHID];    // packed [slot][H]   (32 MB)
__device__ float g_Y [NTOK * 2 * DMODEL];  // packed [slot][D]   (8 MB)
__device__ int   g_cnt [NEXP];
__device__ int   g_base[NEXP];
__device__ float g_imp [NEXP];
__device__ int   g_slot_tok[NEXP * NTOK];  // token id at (expert, pos)
__device__ int   g_tok_e  [NTOK * 2];
__device__ int   g_tok_pos[NTOK * 2];
__device__ float g_tok_g  [NTOK * 2];

// ------------------------- packed f32x2 helpers ---------------------------
__device__ __forceinline__ unsigned long long pack2(float x, float y) {
    unsigned long long r;
    asm("mov.b64 %0, {%1, %2};" : "=l"(r) : "f"(x), "f"(y));
    return r;
}
__device__ __forceinline__ float2 unpack2(unsigned long long v) {
    float2 r;
    asm("mov.b64 {%0, %1}, %2;" : "=f"(r.x), "=f"(r.y) : "l"(v));
    return r;
}

// ------------------------- init -------------------------------------------
__global__ void init_kernel() {
    int i = threadIdx.x;
    if (i < NEXP) { g_cnt[i] = 0; g_imp[i] = 0.f; }
}

// ------------------------- gating: one warp per token ---------------------
__global__ void gate_kernel(const float* __restrict__ x,
                            const float* __restrict__ wg) {
    int gw   = (blockIdx.x * blockDim.x + threadIdx.x) >> 5;
    int lane = threadIdx.x & 31;
    if (gw >= NTOK) return;
    int t    = gw;
    int e    = lane & 15;
    int half = lane >> 4;

    const float* xp = x  + (size_t)t * DMODEL + half * 256;
    const float* wp = wg + (size_t)(half * 256) * NEXP + e;
    float s0 = 0.f, s1 = 0.f, s2 = 0.f, s3 = 0.f;
    #pragma unroll 4
    for (int d = 0; d < 256; d += 4) {
        s0 = fmaf(__ldg(xp + d + 0), __ldg(wp + (d + 0) * NEXP), s0);
        s1 = fmaf(__ldg(xp + d + 1), __ldg(wp + (d + 1) * NEXP), s1);
        s2 = fmaf(__ldg(xp + d + 2), __ldg(wp + (d + 2) * NEXP), s2);
        s3 = fmaf(__ldg(xp + d + 3), __ldg(wp + (d + 3) * NEXP), s3);
    }
    float s = (s0 + s1) + (s2 + s3);
    s += __shfl_xor_sync(0xffffffffu, s, 16);   // lanes 0..15: full dot for expert=lane

    // top-2 (ties -> lower index first, matching jax.lax.top_k)
    float v0 = -1e30f, v1 = -1e30f; int i0 = -1, i1 = -1;
    #pragma unroll
    for (int i = 0; i < 16; ++i) {
        float v = __shfl_sync(0xffffffffu, s, i);
        if (v > v0)      { v1 = v0; i1 = i0; v0 = v; i0 = i; }
        else if (v > v1) { v1 = v;  i1 = i; }
    }

    if (lane == 0) {
        float ex = expf(v1 - v0);          // <= 1, no overflow
        float g0 = 1.f / (1.f + ex);
        float g1 = ex * g0;
        int p0 = atomicAdd(&g_cnt[i0], 1);
        int p1 = atomicAdd(&g_cnt[i1], 1);
        g_slot_tok[i0 * NTOK + p0] = t;
        g_slot_tok[i1 * NTOK + p1] = t;
        g_tok_e  [t * 2 + 0] = i0;  g_tok_pos[t * 2 + 0] = p0;  g_tok_g[t * 2 + 0] = g0;
        g_tok_e  [t * 2 + 1] = i1;  g_tok_pos[t * 2 + 1] = p1;  g_tok_g[t * 2 + 1] = g1;
        atomicAdd(&g_imp[i0], g0);
        atomicAdd(&g_imp[i1], g1);
    }
}

// ------------------------- exclusive scan over 16 counts ------------------
__global__ void scan_kernel() {
    if (threadIdx.x == 0) {
        int acc = 0;
        #pragma unroll
        for (int e = 0; e < NEXP; ++e) { g_base[e] = acc; acc += g_cnt[e]; }
    }
}

// ------------------------- per-expert FFN GEMM ----------------------------
// MODE 0: He = relu(gather(x) @ w1[e] + b1[e])   K=512,  N=2048, BM=128
// MODE 1: Y  = He @ w2[e]                        K=2048, N=512,  BM=64
template<int BM, int MODE>
__global__ void __launch_bounds__(256)
ffn_kernel(const float* __restrict__ Ax,
           const float* __restrict__ W,
           const float* __restrict__ bias) {
    constexpr int BN = 128, BK = 8;
    constexpr int N  = (MODE == 0) ? DHID : DMODEL;
    constexpr int K  = (MODE == 0) ? DMODEL : DHID;
    constexpr int TM = BM / 16;
    constexpr int KT = K / BK;

    const int e   = blockIdx.z;
    const int n_e = g_cnt[e];
    const int m0  = blockIdx.y * BM;
    if (m0 >= n_e) return;
    const int n0   = blockIdx.x * BN;
    const int base = g_base[e];
    const int tid  = threadIdx.x;

    __shared__ __align__(16) float As[2][BK][BM];
    __shared__ __align__(16) float Bs[2][BK][BN];
    __shared__ int s_tok[BM];

    if (MODE == 0) {
        for (int i = tid; i < BM; i += 256) {
            int m = m0 + i;
            s_tok[i] = (m < n_e) ? g_slot_tok[e * NTOK + m] : -1;
        }
        __syncthreads();
    }

    // A-tile loader mapping (BM*BK floats by 256 threads)
    int aRow, aK;
    if (BM == 128) { aRow = tid >> 1; aK = (tid & 1) * 4; }
    else           { aRow = tid >> 2; aK = (tid & 3) * 2; }

    const float* Aptr;
    bool aValid;
    if (MODE == 0) {
        int tok = s_tok[aRow];
        aValid  = (tok >= 0);
        Aptr    = Ax + (size_t)(tok < 0 ? 0 : tok) * DMODEL + aK;
    } else {
        int m  = m0 + aRow;
        aValid = (m < n_e);
        int mc = m < n_e ? m : (n_e - 1);
        Aptr   = g_He + (size_t)(base + mc) * DHID + aK;
    }

    const int bK   = tid >> 5;           // 0..7
    const int bCol = (tid & 31) * 4;     // 0..124
    const float* Bptr = W + (size_t)e * K * N + (size_t)bK * N + n0 + bCol;

    const int row = tid >> 4;            // 0..15
    const int col = tid & 15;            // 0..15

    unsigned long long acc[TM][4];
    #pragma unroll
    for (int i = 0; i < TM; ++i)
        #pragma unroll
        for (int j = 0; j < 4; ++j) acc[i][j] = 0ull;

    float  aR[4];
    float4 bR;
    constexpr int AL = (BM == 128) ? 4 : 2;

    // prefetch tile 0
    if (BM == 128) {
        float4 v = aValid ? *(const float4*)Aptr : make_float4(0.f, 0.f, 0.f, 0.f);
        aR[0] = v.x; aR[1] = v.y; aR[2] = v.z; aR[3] = v.w;
    } else {
        float2 v = aValid ? *(const float2*)Aptr : make_float2(0.f, 0.f);
        aR[0] = v.x; aR[1] = v.y;
    }
    bR = *(const float4*)Bptr;
    #pragma unroll
    for (int j = 0; j < AL; ++j) As[0][aK + j][aRow] = aR[j];
    *(float4*)&Bs[0][bK][bCol] = bR;
    __syncthreads();

    for (int kt = 0; kt < KT; ++kt) {
        const int  cur = kt & 1;
        const bool pf  = (kt + 1 < KT);
        if (pf) {
            const float* ap = Aptr + (size_t)(kt + 1) * BK;
            if (BM == 128) {
                float4 v = aValid ? *(const float4*)ap : make_float4(0.f, 0.f, 0.f, 0.f);
                aR[0] = v.x; aR[1] = v.y; aR[2] = v.z; aR[3] = v.w;
            } else {
                float2 v = aValid ? *(const float2*)ap : make_float2(0.f, 0.f);
                aR[0] = v.x; aR[1] = v.y;
            }
            bR = *(const float4*)(Bptr + (size_t)(kt + 1) * BK * N);
        }
        #pragma unroll
        for (int k = 0; k < BK; ++k) {
            float a[TM];
            #pragma unroll
            for (int i = 0; i < TM; i += 4) {
                float4 t4 = *(const float4*)&As[cur][k][row * TM + i];
                a[i] = t4.x; a[i + 1] = t4.y; a[i + 2] = t4.z; a[i + 3] = t4.w;
            }
            float4 b0 = *(const float4*)&Bs[cur][k][col * 8];
            float4 b1 = *(const float4*)&Bs[cur][k][col * 8 + 4];
            unsigned long long bp[4];
            bp[0] = pack2(b0.x, b0.y); bp[1] = pack2(b0.z, b0.w);
            bp[2] = pack2(b1.x, b1.y); bp[3] = pack2(b1.z, b1.w);
            #pragma unroll
            for (int i = 0; i < TM; ++i) {
                unsigned long long ap2 = pack2(a[i], a[i]);
                #pragma unroll
                for (int j = 0; j < 4; ++j)
                    asm("fma.rn.f32x2 %0, %1, %2, %0;"
                        : "+l"(acc[i][j]) : "l"(ap2), "l"(bp[j]));
            }
        }
        if (pf) {
            const int nxt = cur ^ 1;
            #pragma unroll
            for (int j = 0; j < AL; ++j) As[nxt][aK + j][aRow] = aR[j];
            *(float4*)&Bs[nxt][bK][bCol] = bR;
        }
        __syncthreads();
    }

    if (MODE == 0) {
        const float* bpp = bias + (size_t)e * DHID + n0 + col * 8;
        float4 c0 = *(const float4*)bpp;
        float4 c1 = *(const float4*)(bpp + 4);
        float bv[8] = {c0.x, c0.y, c0.z, c0.w, c1.x, c1.y, c1.z, c1.w};
        #pragma unroll
        for (int i = 0; i < TM; ++i) {
            int m = m0 + row * TM + i;
            if (m < n_e) {
                float* hp = g_He + (size_t)(base + m) * DHID + n0 + col * 8;
                float4 o0, o1; float2 p;
                p = unpack2(acc[i][0]); o0.x = fmaxf(p.x + bv[0], 0.f); o0.y = fmaxf(p.y + bv[1], 0.f);
                p = unpack2(acc[i][1]); o0.z = fmaxf(p.x + bv[2], 0.f); o0.w = fmaxf(p.y + bv[3], 0.f);
                p = unpack2(acc[i][2]); o1.x = fmaxf(p.x + bv[4], 0.f); o1.y = fmaxf(p.y + bv[5], 0.f);
                p = unpack2(acc[i][3]); o1.z = fmaxf(p.x + bv[6], 0.f); o1.w = fmaxf(p.y + bv[7], 0.f);
                *(float4*)hp       = o0;
                *(float4*)(hp + 4) = o1;
            }
        }
    } else {
        #pragma unroll
        for (int i = 0; i < TM; ++i) {
            int m = m0 + row * TM + i;
            if (m < n_e) {
                float* yp = g_Y + (size_t)(base + m) * DMODEL + n0 + col * 8;
                float4 o0, o1; float2 p;
                p = unpack2(acc[i][0]); o0.x = p.x; o0.y = p.y;
                p = unpack2(acc[i][1]); o0.z = p.x; o0.w = p.y;
                p = unpack2(acc[i][2]); o1.x = p.x; o1.y = p.y;
                p = unpack2(acc[i][3]); o1.z = p.x; o1.w = p.y;
                *(float4*)yp       = o0;
                *(float4*)(yp + 4) = o1;
            }
        }
    }
}

// ------------------------- combine: out = sum_k g_k * (Y_k + b2[e_k]) -----
__global__ void combine_kernel(const float* __restrict__ b2,
                               float* __restrict__ out) {
    int idx = blockIdx.x * blockDim.x + threadIdx.x;
    int t   = idx >> 7;            // 128 float4-chunks per token
    int dc  = (idx & 127) * 4;
    if (t >= NTOK) return;
    int   e0 = g_tok_e[t * 2],     e1 = g_tok_e[t * 2 + 1];
    float g0 = g_tok_g[t * 2],     g1 = g_tok_g[t * 2 + 1];
    int   s0 = g_base[e0] + g_tok_pos[t * 2];
    int   s1 = g_base[e1] + g_tok_pos[t * 2 + 1];
    float4 y0 = *(const float4*)(g_Y + (size_t)s0 * DMODEL + dc);
    float4 y1 = *(const float4*)(g_Y + (size_t)s1 * DMODEL + dc);
    float4 c0 = *(const float4*)(b2 + (size_t)e0 * DMODEL + dc);
    float4 c1 = *(const float4*)(b2 + (size_t)e1 * DMODEL + dc);
    float4 o;
    o.x = g0 * (y0.x + c0.x) + g1 * (y1.x + c1.x);
    o.y = g0 * (y0.y + c0.y) + g1 * (y1.y + c1.y);
    o.z = g0 * (y0.z + c0.z) + g1 * (y1.z + c1.z);
    o.w = g0 * (y0.w + c0.w) + g1 * (y1.w + c1.w);
    *(float4*)(out + (size_t)t * DMODEL + dc) = o;
}

// ------------------------- aux loss ----------------------------------------
__global__ void aux_kernel(float* __restrict__ dst) {
    if (threadIdx.x == 0) {
        float v[NEXP]; float s = 0.f;
        #pragma unroll
        for (int e = 0; e < NEXP; ++e) { v[e] = g_imp[e]; s += v[e]; }
        float mean = s / NEXP;
        float ss = 0.f;
        #pragma unroll
        for (int e = 0; e < NEXP; ++e) { float d = v[e] - mean; ss += d * d; }
        float var = ss / (NEXP - 1);           // ddof=1
        dst[0] = 0.01f * var / (mean * mean + 1e-10f);
    }
}

// ------------------------- launch ------------------------------------------
extern "C" void kernel_launch(void* const* d_in, const int* in_sizes, int n_in,
                              void* d_out, int out_size) {
    const float* x  = (const float*)d_in[0];
    const float* wg = (const float*)d_in[1];
    const float* w1 = (const float*)d_in[2];
    const float* b1 = (const float*)d_in[3];
    const float* w2 = (const float*)d_in[4];
    const float* b2 = (const float*)d_in[5];
    float* out = (float*)d_out;

    init_kernel<<<1, 32>>>();
    gate_kernel<<<(NTOK * 32) / 128, 128>>>(x, wg);
    scan_kernel<<<1, 32>>>();

    dim3 grid1(DHID / 128, NTOK / 128, NEXP);   // (16,16,16), early-exit on m0>=cnt
    ffn_kernel<128, 0><<<grid1, 256>>>(x, w1, b1);

    dim3 grid2(DMODEL / 128, NTOK / 64, NEXP);  // (4,32,16)
    ffn_kernel<64, 1><<<grid2, 256>>>(nullptr, w2, nullptr);

    combine_kernel<<<(NTOK * 128) / 256, 256>>>(b2, out);

    if (out_size > NTOK * DMODEL)
        aux_kernel<<<1, 32>>>(out + NTOK * DMODEL);
}